// round 5
// baseline (speedup 1.0000x reference)
#include <cuda_runtime.h>
#include <cuda_fp16.h>
#include <cstdint>

#define N_NODES   100000
#define N_EDGES   1600000
#define VOCAB     128
#define D         30
#define DPAD      32
#define HPAD      16         // half2 per node row (32 features as 16 half2 = 64B)
#define N_CLASSES 5
#define SCAN_NB   98         // 98 * 1024 = 100352 >= N_NODES
#define FLAGBIT   0x40000000

// Scratch (device globals: no allocation allowed)
__device__ __half2 g_hsA[N_NODES * HPAD];
__device__ __half2 g_hsB[N_NODES * HPAD];
__device__ float   g_inv[N_NODES];
__device__ int2    g_xin[N_NODES];              // packed (x[n], inv[n])
__device__ int     g_pre[2 * N_NODES + 128];    // cnt | degr | scan state (memset once)
__device__ int     g_off[N_NODES + 1];
__device__ int     g_cur[N_NODES];
__device__ int     g_srow[N_EDGES];

// ---------------------------------------------------------------------------
__global__ void k_hist(const int* __restrict__ row, const int* __restrict__ col,
                       int* __restrict__ cnt, int* __restrict__ degr) {
    int e = blockIdx.x * blockDim.x + threadIdx.x;
    if (e < N_EDGES) {
        atomicAdd(&cnt[col[e]], 1);
        atomicAdd(&degr[row[e]], 1);
    }
}

// Single-pass scan: 98 blocks x 256 threads x 4 items. Each block publishes its
// aggregate (flag bit in same word -> no fence needed); every block sums the
// aggregates of its predecessors (no chained prefixes => deadlock-free).
// Also emits inv_deg and packed (x, inv).
__global__ void __launch_bounds__(256)
k_scan(const int* __restrict__ cnt, const int* __restrict__ degr,
       const int* __restrict__ x,
       int* __restrict__ off, int* __restrict__ cur,
       float* __restrict__ inv, int2* __restrict__ xin,
       int* __restrict__ state) {
    __shared__ int wsum[8];
    __shared__ int sPrefix;
    int t = threadIdx.x, bid = blockIdx.x;
    int lane = t & 31, wid = t >> 5;
    int base = bid * 1024 + t * 4;

    int v[4];
    #pragma unroll
    for (int j = 0; j < 4; j++) {
        int i = base + j;
        v[j] = (i < N_NODES) ? cnt[i] : 0;
    }
    int tsum = v[0] + v[1] + v[2] + v[3];

    // warp inclusive scan of thread sums
    int inc = tsum;
    #pragma unroll
    for (int d = 1; d < 32; d <<= 1) {
        int u = __shfl_up_sync(~0u, inc, d);
        if (lane >= d) inc += u;
    }
    if (lane == 31) wsum[wid] = inc;
    __syncthreads();
    if (wid == 0) {
        int w = (lane < 8) ? wsum[lane] : 0;
        #pragma unroll
        for (int d = 1; d < 8; d <<= 1) {
            int u = __shfl_up_sync(~0u, w, d);
            if (lane >= d) w += u;
        }
        if (lane < 8) wsum[lane] = w;   // inclusive warp sums
    }
    __syncthreads();
    int blockAgg = wsum[7];
    int warpBase = (wid == 0) ? 0 : wsum[wid - 1];
    int texcl = warpBase + inc - tsum;  // exclusive prefix within block
    __syncthreads();                    // done reading wsum

    if (t == 0) atomicExch(&state[bid], blockAgg | FLAGBIT);

    // poll predecessors' aggregates (bid <= 97 => each thread polls <= 1)
    int pref = 0;
    if (t < bid) {
        int s;
        do { s = atomicOr(&state[t], 0); } while (!(s & FLAGBIT));
        pref = s & ~FLAGBIT;
    }
    #pragma unroll
    for (int d = 16; d > 0; d >>= 1) pref += __shfl_down_sync(~0u, pref, d);
    if (lane == 0) wsum[wid] = pref;
    __syncthreads();
    if (t == 0) {
        int p = 0;
        #pragma unroll
        for (int j = 0; j < 8; j++) p += wsum[j];
        sPrefix = p;
    }
    __syncthreads();

    int e = sPrefix + texcl;
    #pragma unroll
    for (int j = 0; j < 4; j++) {
        int i = base + j;
        if (i < N_NODES) {
            off[i] = e;
            cur[i] = e;
            float iv = 1.0f / (1.0f + (float)degr[i]);   // +1 = self loop
            inv[i] = iv;
            xin[i] = make_int2(x[i], __float_as_int(iv));
            if (i == N_NODES - 1) off[N_NODES] = e + v[j];
        }
        e += v[j];
    }
}

__global__ void k_scatter(const int* __restrict__ row, const int* __restrict__ col,
                          int* __restrict__ cur, int* __restrict__ srow) {
    int e = blockIdx.x * blockDim.x + threadIdx.x;
    if (e < N_EDGES) {
        int p = atomicAdd(&cur[col[e]], 1);
        srow[p] = row[e];
    }
}

// ---------------------------------------------------------------------------
// Layer 1: message = inv[src] * emb[x[src]], emb table in shared memory.
// Per edge we gather only 8B (xin[src]) instead of a 64B feature row.
// 16-lane group per node; accum fp32; epilogue relu(agg@W1^T+b1)*inv -> fp16.
__global__ void __launch_bounds__(256)
k_layer1(const int* __restrict__ off, const int* __restrict__ srow,
         const int2* __restrict__ xin, const float* __restrict__ emb,
         const float* __restrict__ W, const float* __restrict__ b,
         __half2* __restrict__ hs_out) {
    __shared__ float  embs[VOCAB * DPAD];   // 16KB
    __shared__ float2 Wt2[D * 16];
    __shared__ float2 b2s[16];
    __shared__ float  sAgg[16][DPAD];

    int tid = threadIdx.x;
    for (int i = tid; i < VOCAB * DPAD; i += 256) {
        int vv = i >> 5, d = i & 31;
        embs[i] = (d < D) ? emb[vv * D + d] : 0.0f;
    }
    for (int i = tid; i < D * 16; i += 256) {
        int l = i & 15, k = i >> 4;
        float w0 = (2 * l     < D) ? W[(2 * l)     * D + k] : 0.0f;
        float w1 = (2 * l + 1 < D) ? W[(2 * l + 1) * D + k] : 0.0f;
        Wt2[i] = make_float2(w0, w1);
    }
    if (tid < 16) {
        int l = tid;
        b2s[l] = make_float2((2 * l < D) ? b[2 * l] : 0.0f,
                             (2 * l + 1 < D) ? b[2 * l + 1] : 0.0f);
    }
    __syncthreads();

    int g = tid >> 4, l = tid & 15;
    int n = blockIdx.x * 16 + g;
    int f0 = 2 * l, f1 = 2 * l + 1;

    int beg = off[n], end = off[n + 1];
    int2 pn = xin[n];
    float ivn = __int_as_float(pn.y);
    float2 a0, a1, a2, a3;
    a0.x = ivn * embs[(pn.x << 5) + f0];
    a0.y = ivn * embs[(pn.x << 5) + f1];
    a1 = make_float2(0.f, 0.f);
    a2 = make_float2(0.f, 0.f);
    a3 = make_float2(0.f, 0.f);

    int i = beg;
    for (; i + 7 < end; i += 8) {
        int s0 = __ldg(srow + i);     int s1 = __ldg(srow + i + 1);
        int s2 = __ldg(srow + i + 2); int s3 = __ldg(srow + i + 3);
        int s4 = __ldg(srow + i + 4); int s5 = __ldg(srow + i + 5);
        int s6 = __ldg(srow + i + 6); int s7 = __ldg(srow + i + 7);
        int2 p0 = __ldg(xin + s0); int2 p1 = __ldg(xin + s1);
        int2 p2 = __ldg(xin + s2); int2 p3 = __ldg(xin + s3);
        int2 p4 = __ldg(xin + s4); int2 p5 = __ldg(xin + s5);
        int2 p6 = __ldg(xin + s6); int2 p7 = __ldg(xin + s7);
        float w;
        w = __int_as_float(p0.y); a0.x = fmaf(w, embs[(p0.x << 5) + f0], a0.x); a0.y = fmaf(w, embs[(p0.x << 5) + f1], a0.y);
        w = __int_as_float(p1.y); a1.x = fmaf(w, embs[(p1.x << 5) + f0], a1.x); a1.y = fmaf(w, embs[(p1.x << 5) + f1], a1.y);
        w = __int_as_float(p2.y); a2.x = fmaf(w, embs[(p2.x << 5) + f0], a2.x); a2.y = fmaf(w, embs[(p2.x << 5) + f1], a2.y);
        w = __int_as_float(p3.y); a3.x = fmaf(w, embs[(p3.x << 5) + f0], a3.x); a3.y = fmaf(w, embs[(p3.x << 5) + f1], a3.y);
        w = __int_as_float(p4.y); a0.x = fmaf(w, embs[(p4.x << 5) + f0], a0.x); a0.y = fmaf(w, embs[(p4.x << 5) + f1], a0.y);
        w = __int_as_float(p5.y); a1.x = fmaf(w, embs[(p5.x << 5) + f0], a1.x); a1.y = fmaf(w, embs[(p5.x << 5) + f1], a1.y);
        w = __int_as_float(p6.y); a2.x = fmaf(w, embs[(p6.x << 5) + f0], a2.x); a2.y = fmaf(w, embs[(p6.x << 5) + f1], a2.y);
        w = __int_as_float(p7.y); a3.x = fmaf(w, embs[(p7.x << 5) + f0], a3.x); a3.y = fmaf(w, embs[(p7.x << 5) + f1], a3.y);
    }
    for (; i < end; i++) {
        int2 p = __ldg(xin + __ldg(srow + i));
        float w = __int_as_float(p.y);
        a0.x = fmaf(w, embs[(p.x << 5) + f0], a0.x);
        a0.y = fmaf(w, embs[(p.x << 5) + f1], a0.y);
    }
    sAgg[g][f0] = a0.x + a1.x + a2.x + a3.x;
    sAgg[g][f1] = a0.y + a1.y + a2.y + a3.y;
    __syncwarp();

    float2 o = b2s[l];
    #pragma unroll
    for (int k = 0; k < D; k++) {
        float av = sAgg[g][k];
        float2 wv = Wt2[(k << 4) + l];
        o.x = fmaf(av, wv.x, o.x);
        o.y = fmaf(av, wv.y, o.y);
    }
    o.x = fmaxf(o.x, 0.0f);
    o.y = fmaxf(o.y, 0.0f);
    if (f0 >= D) o.x = 0.0f;
    if (f1 >= D) o.y = 0.0f;
    hs_out[(n << 4) + l] = __floats2half2_rn(o.x * ivn, o.y * ivn);
}

// Layers 2/3: fp16 feature-row gather (as in R3).
template <bool FINAL>
__global__ void __launch_bounds__(256)
k_layer(const int* __restrict__ off, const int* __restrict__ srow,
        const __half2* __restrict__ hs,
        const float* __restrict__ W, const float* __restrict__ b,
        const float* __restrict__ inv,
        __half2* __restrict__ hs_out,
        const float* __restrict__ Wout, const float* __restrict__ bout,
        float* __restrict__ out) {
    __shared__ float2 Wt2[D * 16];
    __shared__ float2 b2s[16];
    __shared__ float  sAgg[16][DPAD];
    __shared__ float  Wo[N_CLASSES * D];
    __shared__ float  bo[N_CLASSES];

    int tid = threadIdx.x;
    for (int i = tid; i < D * 16; i += 256) {
        int l = i & 15, k = i >> 4;
        float w0 = (2 * l     < D) ? W[(2 * l)     * D + k] : 0.0f;
        float w1 = (2 * l + 1 < D) ? W[(2 * l + 1) * D + k] : 0.0f;
        Wt2[i] = make_float2(w0, w1);
    }
    if (tid < 16) {
        int l = tid;
        b2s[l] = make_float2((2 * l < D) ? b[2 * l] : 0.0f,
                             (2 * l + 1 < D) ? b[2 * l + 1] : 0.0f);
    }
    if (FINAL) {
        if (tid < N_CLASSES * D) Wo[tid] = Wout[tid];
        if (tid < N_CLASSES)     bo[tid] = bout[tid];
    }
    __syncthreads();

    int g = tid >> 4, l = tid & 15;
    int n = blockIdx.x * 16 + g;

    int beg = off[n], end = off[n + 1];
    float2 a0 = __half22float2(hs[(n << 4) + l]);   // self loop
    float2 a1 = make_float2(0.f, 0.f);
    float2 a2 = make_float2(0.f, 0.f);
    float2 a3 = make_float2(0.f, 0.f);
    int i = beg;
    for (; i + 3 < end; i += 4) {
        int s0 = __ldg(srow + i);
        int s1 = __ldg(srow + i + 1);
        int s2 = __ldg(srow + i + 2);
        int s3 = __ldg(srow + i + 3);
        float2 v0 = __half22float2(hs[(s0 << 4) + l]);
        float2 v1 = __half22float2(hs[(s1 << 4) + l]);
        float2 v2 = __half22float2(hs[(s2 << 4) + l]);
        float2 v3 = __half22float2(hs[(s3 << 4) + l]);
        a0.x += v0.x; a0.y += v0.y;
        a1.x += v1.x; a1.y += v1.y;
        a2.x += v2.x; a2.y += v2.y;
        a3.x += v3.x; a3.y += v3.y;
    }
    for (; i < end; i++) {
        float2 v = __half22float2(hs[(__ldg(srow + i) << 4) + l]);
        a0.x += v.x; a0.y += v.y;
    }
    sAgg[g][2 * l]     = a0.x + a1.x + a2.x + a3.x;
    sAgg[g][2 * l + 1] = a0.y + a1.y + a2.y + a3.y;
    __syncwarp();

    float2 o = b2s[l];
    #pragma unroll
    for (int k = 0; k < D; k++) {
        float av = sAgg[g][k];
        float2 w = Wt2[(k << 4) + l];
        o.x = fmaf(av, w.x, o.x);
        o.y = fmaf(av, w.y, o.y);
    }
    o.x = fmaxf(o.x, 0.0f);
    o.y = fmaxf(o.y, 0.0f);
    if (2 * l >= D)     o.x = 0.0f;
    if (2 * l + 1 >= D) o.y = 0.0f;

    if (!FINAL) {
        float iv = inv[n];
        hs_out[(n << 4) + l] = __floats2half2_rn(o.x * iv, o.y * iv);
    } else {
        __syncwarp();
        sAgg[g][2 * l]     = o.x;
        sAgg[g][2 * l + 1] = o.y;
        __syncwarp();
        if (l < N_CLASSES) {
            float acc = bo[l];
            #pragma unroll
            for (int k = 0; k < D; k++)
                acc = fmaf(sAgg[g][k], Wo[l * D + k], acc);
            out[n * N_CLASSES + l] = acc;
        }
    }
}

// ---------------------------------------------------------------------------
extern "C" void kernel_launch(void* const* d_in, const int* in_sizes, int n_in,
                              void* d_out, int out_size) {
    const int*   x    = (const int*)  d_in[0];
    const int*   ei   = (const int*)  d_in[1];   // [2, E] row-major
    const float* emb  = (const float*)d_in[2];
    const float* W1   = (const float*)d_in[3];
    const float* b1   = (const float*)d_in[4];
    const float* W2   = (const float*)d_in[5];
    const float* b2   = (const float*)d_in[6];
    const float* W3   = (const float*)d_in[7];
    const float* b3   = (const float*)d_in[8];
    const float* Wout = (const float*)d_in[9];
    const float* bout = (const float*)d_in[10];
    float* out = (float*)d_out;

    const int* row = ei;
    const int* col = ei + N_EDGES;

    __half2 *hsA, *hsB;
    float *inv;
    int2 *xin;
    int *pre, *off, *cur, *srow;
    cudaGetSymbolAddress((void**)&hsA,  g_hsA);
    cudaGetSymbolAddress((void**)&hsB,  g_hsB);
    cudaGetSymbolAddress((void**)&inv,  g_inv);
    cudaGetSymbolAddress((void**)&xin,  g_xin);
    cudaGetSymbolAddress((void**)&pre,  g_pre);
    cudaGetSymbolAddress((void**)&off,  g_off);
    cudaGetSymbolAddress((void**)&cur,  g_cur);
    cudaGetSymbolAddress((void**)&srow, g_srow);

    int* cnt   = pre;
    int* degr  = pre + N_NODES;
    int* state = pre + 2 * N_NODES;

    const int NT = 256;
    const int gEdge  = N_EDGES / NT;    // 6250 exact
    const int gLayer = N_NODES / 16;    // 6250 exact

    // 1. zero cnt/degr/state in one shot
    cudaMemsetAsync(pre, 0, (2 * N_NODES + 128) * sizeof(int));
    // 2. degree histograms
    k_hist<<<gEdge, NT>>>(row, col, cnt, degr);
    // 3. single-pass scan -> off/cur + inv_deg + packed (x, inv)
    k_scan<<<SCAN_NB, NT>>>(cnt, degr, x, off, cur, inv, xin, state);
    // 4. counting-sort edges by destination
    k_scatter<<<gEdge, NT>>>(row, col, cur, srow);

    // 5-7. three fused layers (layer1 reads only 8B/edge via smem emb table)
    k_layer1<<<gLayer, NT>>>(off, srow, xin, emb, W1, b1, hsA);
    k_layer<false><<<gLayer, NT>>>(off, srow, hsA, W2, b2, inv, hsB,
                                   nullptr, nullptr, nullptr);
    k_layer<true> <<<gLayer, NT>>>(off, srow, hsB, W3, b3, inv, nullptr,
                                   Wout, bout, out);
}

// round 6
// speedup vs baseline: 1.1583x; 1.1583x over previous
#include <cuda_runtime.h>
#include <cuda_fp16.h>
#include <cstdint>

#define N_NODES   100000
#define N_EDGES   1600000
#define VOCAB     128
#define D         30
#define DPAD      32
#define N_CLASSES 5
#define SCAN_NB   98         // 98 * 1024 = 100352 >= N_NODES
#define FLAGBIT   0x40000000
#define NPB       64         // nodes per block in layer kernels

// Scratch (device globals; float4 arrays => 16B alignment for LDG.128)
__device__ float4 g_hsA[N_NODES * 4];           // fp16 features: 64B/node = 4 float4
__device__ float4 g_hsB[N_NODES * 4];
__device__ float  g_inv[N_NODES];
__device__ int    g_pre[2 * N_NODES + 128];     // cnt | degr | scan state (memset once)
__device__ int    g_off[N_NODES + 1];
__device__ int    g_cur[N_NODES];
__device__ int    g_srow[N_EDGES];

// ---------------------------------------------------------------------------
__global__ void k_hist(const int* __restrict__ row, const int* __restrict__ col,
                       int* __restrict__ cnt, int* __restrict__ degr) {
    int e = blockIdx.x * blockDim.x + threadIdx.x;
    if (e < N_EDGES) {
        atomicAdd(&cnt[col[e]], 1);
        atomicAdd(&degr[row[e]], 1);
    }
}

// Single-pass scan (98 blocks x 256 thr x 4 items): off/cur + inv_deg + hs0.
// Each block publishes aggregate|FLAG in one word; every block sums its
// predecessors' aggregates directly (no chaining => deadlock-free).
__global__ void __launch_bounds__(256)
k_scan(const int* __restrict__ cnt, const int* __restrict__ degr,
       const int* __restrict__ x, const float* __restrict__ emb,
       int* __restrict__ off, int* __restrict__ cur,
       float* __restrict__ inv, __half2* __restrict__ hs0,
       int* __restrict__ state) {
    __shared__ int wsum[8];
    __shared__ int sPrefix;
    int t = threadIdx.x, bid = blockIdx.x;
    int lane = t & 31, wid = t >> 5;
    int base = bid * 1024 + t * 4;

    int v[4];
    #pragma unroll
    for (int j = 0; j < 4; j++) {
        int i = base + j;
        v[j] = (i < N_NODES) ? cnt[i] : 0;
    }
    int tsum = v[0] + v[1] + v[2] + v[3];

    int inc = tsum;
    #pragma unroll
    for (int d = 1; d < 32; d <<= 1) {
        int u = __shfl_up_sync(~0u, inc, d);
        if (lane >= d) inc += u;
    }
    if (lane == 31) wsum[wid] = inc;
    __syncthreads();
    if (wid == 0) {
        int w = (lane < 8) ? wsum[lane] : 0;
        #pragma unroll
        for (int d = 1; d < 8; d <<= 1) {
            int u = __shfl_up_sync(~0u, w, d);
            if (lane >= d) w += u;
        }
        if (lane < 8) wsum[lane] = w;
    }
    __syncthreads();
    int warpBase = (wid == 0) ? 0 : wsum[wid - 1];
    int texcl = warpBase + inc - tsum;
    int blockAgg = wsum[7];
    __syncthreads();

    if (t == 0) atomicExch(&state[bid], blockAgg | FLAGBIT);

    int pref = 0;
    if (t < bid) {
        int s;
        do { s = atomicOr(&state[t], 0); } while (!(s & FLAGBIT));
        pref = s & ~FLAGBIT;
    }
    #pragma unroll
    for (int d = 16; d > 0; d >>= 1) pref += __shfl_down_sync(~0u, pref, d);
    if (lane == 0) wsum[wid] = pref;
    __syncthreads();
    if (t == 0) {
        int p = 0;
        #pragma unroll
        for (int j = 0; j < 8; j++) p += wsum[j];
        sPrefix = p;
    }
    __syncthreads();

    int e = sPrefix + texcl;
    #pragma unroll
    for (int j = 0; j < 4; j++) {
        int i = base + j;
        if (i < N_NODES) {
            off[i] = e;
            cur[i] = e;
            float iv = 1.0f / (1.0f + (float)degr[i]);   // +1 = self loop
            inv[i] = iv;
            // hs0[i] = fp16(emb[x[i]] * iv)
            const float* er = emb + x[i] * D;
            __half2* hrow = hs0 + i * 16;
            #pragma unroll
            for (int d = 0; d < 15; d++)
                hrow[d] = __floats2half2_rn(er[2 * d] * iv, er[2 * d + 1] * iv);
            hrow[15] = __floats2half2_rn(0.0f, 0.0f);
            if (i == N_NODES - 1) off[N_NODES] = e + v[j];
        }
        e += v[j];
    }
}

__global__ void k_scatter(const int* __restrict__ row, const int* __restrict__ col,
                          int* __restrict__ cur, int* __restrict__ srow) {
    int e = blockIdx.x * blockDim.x + threadIdx.x;
    if (e < N_EDGES) {
        int p = atomicAdd(&cur[col[e]], 1);
        srow[p] = row[e];
    }
}

// ---------------------------------------------------------------------------
// Fused layer. Phase 1: 4 lanes per node, LDG.128 gathers a full 64B fp16 row
// per edge (fp32 accumulation, no atomics) -> sAgg. Phase 2: 16-lane x float2
// matmul epilogue over 4 passes; FINAL emits 5-class logits.
template <bool FINAL>
__global__ void __launch_bounds__(256)
k_layer(const int* __restrict__ off, const int* __restrict__ srow,
        const float4* __restrict__ hs,
        const float* __restrict__ W, const float* __restrict__ b,
        const float* __restrict__ inv,
        __half2* __restrict__ hs_out,
        const float* __restrict__ Wout, const float* __restrict__ bout,
        float* __restrict__ out) {
    __shared__ float  sAgg[NPB][33];
    __shared__ float2 Wt2[D * 16];     // Wt2[k*16+l] = (W[2l][k], W[2l+1][k])
    __shared__ float2 b2s[16];
    __shared__ float  Wo[N_CLASSES * D];
    __shared__ float  bo[N_CLASSES];

    int tid = threadIdx.x;
    for (int i = tid; i < D * 16; i += 256) {
        int l = i & 15, k = i >> 4;
        float w0 = (2 * l     < D) ? W[(2 * l)     * D + k] : 0.0f;
        float w1 = (2 * l + 1 < D) ? W[(2 * l + 1) * D + k] : 0.0f;
        Wt2[i] = make_float2(w0, w1);
    }
    if (tid < 16) {
        int l = tid;
        b2s[l] = make_float2((2 * l < D) ? b[2 * l] : 0.0f,
                             (2 * l + 1 < D) ? b[2 * l + 1] : 0.0f);
    }
    if (FINAL) {
        if (tid < N_CLASSES * D) Wo[tid] = Wout[tid];
        if (tid < N_CLASSES)     bo[tid] = bout[tid];
    }

    // ---- Phase 1: aggregation (4 lanes per node) ----
    {
        int g = tid >> 2, lane = tid & 3;
        int n = blockIdx.x * NPB + g;
        if (n >= N_NODES) n = N_NODES - 1;       // clamp: benign duplicates

        int beg = off[n], end = off[n + 1];
        // self loop
        float4 sv = __ldg(hs + (n << 2) + lane);
        float2 a0 = __half22float2(*(const __half2*)&sv.x);
        float2 a1 = __half22float2(*(const __half2*)&sv.y);
        float2 a2 = __half22float2(*(const __half2*)&sv.z);
        float2 a3 = __half22float2(*(const __half2*)&sv.w);

        int i = beg;
        for (; i + 3 < end; i += 4) {
            int s0 = __ldg(srow + i);
            int s1 = __ldg(srow + i + 1);
            int s2 = __ldg(srow + i + 2);
            int s3 = __ldg(srow + i + 3);
            float4 v0 = __ldg(hs + (s0 << 2) + lane);
            float4 v1 = __ldg(hs + (s1 << 2) + lane);
            float4 v2 = __ldg(hs + (s2 << 2) + lane);
            float4 v3 = __ldg(hs + (s3 << 2) + lane);
            float2 u;
            u = __half22float2(*(const __half2*)&v0.x); a0.x += u.x; a0.y += u.y;
            u = __half22float2(*(const __half2*)&v0.y); a1.x += u.x; a1.y += u.y;
            u = __half22float2(*(const __half2*)&v0.z); a2.x += u.x; a2.y += u.y;
            u = __half22float2(*(const __half2*)&v0.w); a3.x += u.x; a3.y += u.y;
            u = __half22float2(*(const __half2*)&v1.x); a0.x += u.x; a0.y += u.y;
            u = __half22float2(*(const __half2*)&v1.y); a1.x += u.x; a1.y += u.y;
            u = __half22float2(*(const __half2*)&v1.z); a2.x += u.x; a2.y += u.y;
            u = __half22float2(*(const __half2*)&v1.w); a3.x += u.x; a3.y += u.y;
            u = __half22float2(*(const __half2*)&v2.x); a0.x += u.x; a0.y += u.y;
            u = __half22float2(*(const __half2*)&v2.y); a1.x += u.x; a1.y += u.y;
            u = __half22float2(*(const __half2*)&v2.z); a2.x += u.x; a2.y += u.y;
            u = __half22float2(*(const __half2*)&v2.w); a3.x += u.x; a3.y += u.y;
            u = __half22float2(*(const __half2*)&v3.x); a0.x += u.x; a0.y += u.y;
            u = __half22float2(*(const __half2*)&v3.y); a1.x += u.x; a1.y += u.y;
            u = __half22float2(*(const __half2*)&v3.z); a2.x += u.x; a2.y += u.y;
            u = __half22float2(*(const __half2*)&v3.w); a3.x += u.x; a3.y += u.y;
        }
        for (; i < end; i++) {
            int s0 = __ldg(srow + i);
            float4 v0 = __ldg(hs + (s0 << 2) + lane);
            float2 u;
            u = __half22float2(*(const __half2*)&v0.x); a0.x += u.x; a0.y += u.y;
            u = __half22float2(*(const __half2*)&v0.y); a1.x += u.x; a1.y += u.y;
            u = __half22float2(*(const __half2*)&v0.z); a2.x += u.x; a2.y += u.y;
            u = __half22float2(*(const __half2*)&v0.w); a3.x += u.x; a3.y += u.y;
        }
        float* row = &sAgg[g][lane * 8];
        row[0] = a0.x; row[1] = a0.y; row[2] = a1.x; row[3] = a1.y;
        row[4] = a2.x; row[5] = a2.y; row[6] = a3.x; row[7] = a3.y;
    }
    __syncthreads();

    // ---- Phase 2: matmul + relu (+ final projection), 16 lanes/node, 4 passes ----
    int l = tid & 15, g2 = tid >> 4;           // g2 in 0..15
    #pragma unroll
    for (int p = 0; p < 4; p++) {
        int gl = p * 16 + g2;                  // local node 0..63
        int n = blockIdx.x * NPB + gl;
        if (n >= N_NODES) n = N_NODES - 1;     // clamp: benign duplicates

        float2 o = b2s[l];
        #pragma unroll
        for (int k = 0; k < D; k++) {
            float av = sAgg[gl][k];
            float2 w = Wt2[(k << 4) + l];
            o.x = fmaf(av, w.x, o.x);
            o.y = fmaf(av, w.y, o.y);
        }
        o.x = fmaxf(o.x, 0.0f);
        o.y = fmaxf(o.y, 0.0f);
        if (2 * l >= D)     o.x = 0.0f;
        if (2 * l + 1 >= D) o.y = 0.0f;

        if (!FINAL) {
            float iv = inv[n];
            hs_out[(n << 4) + l] = __floats2half2_rn(o.x * iv, o.y * iv);
        } else {
            __syncwarp();                      // done reading sAgg[gl]
            sAgg[gl][2 * l]     = o.x;
            sAgg[gl][2 * l + 1] = o.y;
            __syncwarp();
            if (l < N_CLASSES) {
                float acc = bo[l];
                #pragma unroll
                for (int k = 0; k < D; k++)
                    acc = fmaf(sAgg[gl][k], Wo[l * D + k], acc);
                out[n * N_CLASSES + l] = acc;
            }
            __syncwarp();
        }
    }
}

// ---------------------------------------------------------------------------
extern "C" void kernel_launch(void* const* d_in, const int* in_sizes, int n_in,
                              void* d_out, int out_size) {
    const int*   x    = (const int*)  d_in[0];
    const int*   ei   = (const int*)  d_in[1];   // [2, E] row-major
    const float* emb  = (const float*)d_in[2];
    const float* W1   = (const float*)d_in[3];
    const float* b1   = (const float*)d_in[4];
    const float* W2   = (const float*)d_in[5];
    const float* b2   = (const float*)d_in[6];
    const float* W3   = (const float*)d_in[7];
    const float* b3   = (const float*)d_in[8];
    const float* Wout = (const float*)d_in[9];
    const float* bout = (const float*)d_in[10];
    float* out = (float*)d_out;

    const int* row = ei;
    const int* col = ei + N_EDGES;

    float4 *hsA, *hsB;
    float *inv;
    int *pre, *off, *cur, *srow;
    cudaGetSymbolAddress((void**)&hsA,  g_hsA);
    cudaGetSymbolAddress((void**)&hsB,  g_hsB);
    cudaGetSymbolAddress((void**)&inv,  g_inv);
    cudaGetSymbolAddress((void**)&pre,  g_pre);
    cudaGetSymbolAddress((void**)&off,  g_off);
    cudaGetSymbolAddress((void**)&cur,  g_cur);
    cudaGetSymbolAddress((void**)&srow, g_srow);

    int* cnt   = pre;
    int* degr  = pre + N_NODES;
    int* state = pre + 2 * N_NODES;

    const int NT = 256;
    const int gEdge  = N_EDGES / NT;             // 6250 exact
    const int gLayer = (N_NODES + NPB - 1) / NPB; // 1563

    cudaMemsetAsync(pre, 0, (2 * N_NODES + 128) * sizeof(int));
    k_hist<<<gEdge, NT>>>(row, col, cnt, degr);
    k_scan<<<SCAN_NB, NT>>>(cnt, degr, x, emb, off, cur, inv,
                            (__half2*)hsA, state);
    k_scatter<<<gEdge, NT>>>(row, col, cur, srow);

    k_layer<false><<<gLayer, NT>>>(off, srow, hsA, W1, b1, inv, (__half2*)hsB,
                                   nullptr, nullptr, nullptr);
    k_layer<false><<<gLayer, NT>>>(off, srow, hsB, W2, b2, inv, (__half2*)hsA,
                                   nullptr, nullptr, nullptr);
    k_layer<true> <<<gLayer, NT>>>(off, srow, hsA, W3, b3, inv, nullptr,
                                   Wout, bout, out);
}